// round 1
// baseline (speedup 1.0000x reference)
#include <cuda_runtime.h>
#include <cstdint>

// Problem constants
constexpr int N_PTS   = 131072;
constexpr int D       = 128;
constexpr int P       = 64;
constexpr int TILE    = 32;
constexpr int THREADS = 512;
constexpr int NTILES  = N_PTS / TILE;   // 4096
constexpr int GRID    = 148;

// smem layout (floats)
// W1s: 16384  (k-major, xor-swizzled float4 within each 128-float row, pre-scaled by g1)
// W2s: 16384  (same, g2)
// Fs : 4096   (feature tile; reused as H2 tile after GEMM2)
// H1s: 4096
// b1s: 128, b2s: 128
// pl : 640    (nx,ny,nz,pdot,minx,miny,minz,maxx,maxy,maxz — 64 each)
// ctr: 4
// pms: 64 u32 (per-plane point bitmask for the current tile)
constexpr int OFF_W1  = 0;
constexpr int OFF_W2  = OFF_W1 + 16384;
constexpr int OFF_FS  = OFF_W2 + 16384;
constexpr int OFF_H1  = OFF_FS + 4096;
constexpr int OFF_B1  = OFF_H1 + 4096;
constexpr int OFF_B2  = OFF_B1 + 128;
constexpr int OFF_PL  = OFF_B2 + 128;
constexpr int OFF_CTR = OFF_PL + 640;
constexpr int OFF_PMS = OFF_CTR + 4;          // u32[64]
constexpr int SMEM_FLOATS = OFF_PMS + 64;
constexpr size_t SMEM_BYTES = SMEM_FLOATS * sizeof(float);  // 167,696 B

__device__ __forceinline__ void fma_row(float acc[4], float as, const float4 b) {
    acc[0] = fmaf(as, b.x, acc[0]);
    acc[1] = fmaf(as, b.y, acc[1]);
    acc[2] = fmaf(as, b.z, acc[2]);
    acc[3] = fmaf(as, b.w, acc[3]);
}

// One 32x128 layer: Out = relu(A @ Wk + bias). Wk is k-major xor-swizzled, g pre-folded.
__device__ __forceinline__ void gemm_tile(const float* __restrict__ A,
                                          const float* __restrict__ Wk,
                                          const float* __restrict__ bias,
                                          float* __restrict__ Out, int tid)
{
    const int oc = tid & 31;          // 4-dim group
    const int p0 = (tid >> 5) * 2;    // 2 points
    float acc0[4] = {0.f, 0.f, 0.f, 0.f};
    float acc1[4] = {0.f, 0.f, 0.f, 0.f};
    const float4* A4 = (const float4*)A;
    const float4* W4 = (const float4*)Wk;
#pragma unroll 4
    for (int kk = 0; kk < 128; kk += 4) {
        const int k4 = kk >> 2;
        float4 a0 = A4[p0 * 32 + k4];
        float4 a1 = A4[(p0 + 1) * 32 + k4];
        float4 w0 = W4[(kk + 0) * 32 + (oc ^ ((kk + 0) & 31))];
        float4 w1 = W4[(kk + 1) * 32 + (oc ^ ((kk + 1) & 31))];
        float4 w2 = W4[(kk + 2) * 32 + (oc ^ ((kk + 2) & 31))];
        float4 w3 = W4[(kk + 3) * 32 + (oc ^ ((kk + 3) & 31))];
        fma_row(acc0, a0.x, w0); fma_row(acc0, a0.y, w1);
        fma_row(acc0, a0.z, w2); fma_row(acc0, a0.w, w3);
        fma_row(acc1, a1.x, w0); fma_row(acc1, a1.y, w1);
        fma_row(acc1, a1.z, w2); fma_row(acc1, a1.w, w3);
    }
    const float4 bb = ((const float4*)bias)[oc];
    float4 r0, r1;
    r0.x = fmaxf(acc0[0] + bb.x, 0.f); r0.y = fmaxf(acc0[1] + bb.y, 0.f);
    r0.z = fmaxf(acc0[2] + bb.z, 0.f); r0.w = fmaxf(acc0[3] + bb.w, 0.f);
    r1.x = fmaxf(acc1[0] + bb.x, 0.f); r1.y = fmaxf(acc1[1] + bb.y, 0.f);
    r1.z = fmaxf(acc1[2] + bb.z, 0.f); r1.w = fmaxf(acc1[3] + bb.w, 0.f);
    ((float4*)Out)[p0 * 32 + oc]       = r0;
    ((float4*)Out)[(p0 + 1) * 32 + oc] = r1;
}

__global__ void __launch_bounds__(THREADS, 1)
plane_refine_fused(const float* __restrict__ feature, const float* __restrict__ xyz,
                   const float* __restrict__ centers,
                   const float* __restrict__ plane_center, const float* __restrict__ plane_normal,
                   const float* __restrict__ plane_min, const float* __restrict__ plane_max,
                   const float* __restrict__ W1, const float* __restrict__ g1,
                   const float* __restrict__ b1,
                   const float* __restrict__ W2, const float* __restrict__ g2,
                   const float* __restrict__ b2,
                   float* __restrict__ out)
{
    extern __shared__ float smem[];
    float* W1s = smem + OFF_W1;
    float* W2s = smem + OFF_W2;
    float* Fs  = smem + OFF_FS;    // also H2 tile
    float* H1s = smem + OFF_H1;
    float* b1s = smem + OFF_B1;
    float* b2s = smem + OFF_B2;
    float* pl  = smem + OFF_PL;
    float* ctr = smem + OFF_CTR;
    unsigned* pms = (unsigned*)(smem + OFF_PMS);

    const int tid  = threadIdx.x;
    const int lane = tid & 31;
    const int warp = tid >> 5;      // 0..15

    // ---- prologue: weights (k-major, swizzled, g folded), biases, plane constants ----
    for (int idx = tid; idx < 16384; idx += THREADS) {
        const int o = idx >> 7, k = idx & 127;
        const int f4  = (k << 5) + ((o >> 2) ^ (k & 31));
        const int pos = (f4 << 2) + (o & 3);
        W1s[pos] = W1[idx] * g1[o];
        W2s[pos] = W2[idx] * g2[o];
    }
    if (tid < 128) { b1s[tid] = b1[tid]; b2s[tid] = b2[tid]; }
    if (tid < P) {
        const float nx = plane_normal[tid * 3 + 0];
        const float ny = plane_normal[tid * 3 + 1];
        const float nz = plane_normal[tid * 3 + 2];
        pl[tid]        = nx;
        pl[64 + tid]   = ny;
        pl[128 + tid]  = nz;
        pl[192 + tid]  = plane_center[tid * 3 + 0] * nx
                       + plane_center[tid * 3 + 1] * ny
                       + plane_center[tid * 3 + 2] * nz;
        pl[256 + tid]  = plane_min[tid * 3 + 0];
        pl[320 + tid]  = plane_min[tid * 3 + 1];
        pl[384 + tid]  = plane_min[tid * 3 + 2];
        pl[448 + tid]  = plane_max[tid * 3 + 0];
        pl[512 + tid]  = plane_max[tid * 3 + 1];
        pl[576 + tid]  = plane_max[tid * 3 + 2];
    }
    if (tid < 3) ctr[tid] = centers[tid];
    __syncthreads();

    const float cx = ctr[0], cy = ctr[1], cz = ctr[2];

    // per-warp persistent pool: warp owns planes 4*warp..4*warp+3; lane owns dims lane*4..+3
    float4 poolv[4];
#pragma unroll
    for (int j = 0; j < 4; j++) poolv[j] = make_float4(0.f, 0.f, 0.f, 0.f);

    for (int t = blockIdx.x; t < NTILES; t += gridDim.x) {
        const int base = t * TILE;
        __syncthreads();   // previous tile's pooling reads of Fs/pms are done

        // load feature tile (32x128 fp32 = 1024 float4)
        {
            const float4* src = (const float4*)(feature + (size_t)base * D);
            float4* dst = (float4*)Fs;
            for (int i = tid; i < 1024; i += THREADS) dst[i] = src[i];
        }
        // masks: lane <-> point, warp w covers planes 4w..4w+3
        {
            const float px = xyz[(size_t)(base + lane) * 3 + 0] + cx;
            const float py = xyz[(size_t)(base + lane) * 3 + 1] + cy;
            const float pz = xyz[(size_t)(base + lane) * 3 + 2] + cz;
#pragma unroll
            for (int j = 0; j < 4; j++) {
                const int p = warp * 4 + j;
                const float d = fabsf(px * pl[p] + py * pl[64 + p] + pz * pl[128 + p]
                                      - pl[192 + p]);
                bool ok = d < 0.05f;
                float mn, mx;
                mn = pl[256 + p]; mx = pl[448 + p];
                ok = ok && ((px >= mn && px < mx) || (mx == 0.f));
                mn = pl[320 + p]; mx = pl[512 + p];
                ok = ok && ((py >= mn && py < mx) || (mx == 0.f));
                mn = pl[384 + p]; mx = pl[576 + p];
                ok = ok && ((pz >= mn && pz < mx) || (mx == 0.f));
                const unsigned bal = __ballot_sync(0xffffffffu, ok);
                if (lane == 0) pms[p] = bal;
            }
        }
        __syncthreads();

        gemm_tile(Fs, W1s, b1s, H1s, tid);   // layer 1
        __syncthreads();
        gemm_tile(H1s, W2s, b2s, Fs, tid);   // layer 2 -> H2 (reuses Fs)
        __syncthreads();

        // pooling: warp-owned planes, register accumulators
        {
            const float4* H2 = (const float4*)Fs;
#pragma unroll
            for (int j = 0; j < 4; j++) {
                unsigned bits = pms[warp * 4 + j];
                while (bits) {
                    const int i = __ffs(bits) - 1;
                    bits &= bits - 1;
                    const float4 v = H2[i * 32 + lane];
                    poolv[j].x = fmaxf(poolv[j].x, v.x);
                    poolv[j].y = fmaxf(poolv[j].y, v.y);
                    poolv[j].z = fmaxf(poolv[j].z, v.z);
                    poolv[j].w = fmaxf(poolv[j].w, v.w);
                }
            }
        }
    }

    // merge: nonneg floats -> uint atomicMax is exact fp max
    {
        unsigned* o32 = (unsigned*)out;
#pragma unroll
        for (int j = 0; j < 4; j++) {
            const int p = warp * 4 + j;
            const int bidx = p * D + lane * 4;
            atomicMax(&o32[bidx + 0], __float_as_uint(poolv[j].x));
            atomicMax(&o32[bidx + 1], __float_as_uint(poolv[j].y));
            atomicMax(&o32[bidx + 2], __float_as_uint(poolv[j].z));
            atomicMax(&o32[bidx + 3], __float_as_uint(poolv[j].w));
        }
    }
}

__global__ void zero_out_kernel(float* __restrict__ out, int n) {
    const int i = blockIdx.x * blockDim.x + threadIdx.x;
    if (i < n) out[i] = 0.f;
}

extern "C" void kernel_launch(void* const* d_in, const int* in_sizes, int n_in,
                              void* d_out, int out_size)
{
    const float* feature      = (const float*)d_in[0];
    const float* xyz          = (const float*)d_in[1];
    const float* centers      = (const float*)d_in[2];
    const float* plane_center = (const float*)d_in[3];
    const float* plane_normal = (const float*)d_in[4];
    const float* plane_min    = (const float*)d_in[5];
    const float* plane_max    = (const float*)d_in[6];
    const float* W1           = (const float*)d_in[7];
    const float* g1           = (const float*)d_in[8];
    const float* b1           = (const float*)d_in[9];
    const float* W2           = (const float*)d_in[10];
    const float* g2           = (const float*)d_in[11];
    const float* b2           = (const float*)d_in[12];
    float* out = (float*)d_out;

    cudaFuncSetAttribute(plane_refine_fused,
                         cudaFuncAttributeMaxDynamicSharedMemorySize, (int)SMEM_BYTES);

    zero_out_kernel<<<(P * D + 255) / 256, 256>>>(out, P * D);
    plane_refine_fused<<<GRID, THREADS, SMEM_BYTES>>>(
        feature, xyz, centers, plane_center, plane_normal, plane_min, plane_max,
        W1, g1, b1, W2, g2, b2, out);
}

// round 5
// speedup vs baseline: 3.1635x; 3.1635x over previous
#include <cuda_runtime.h>
#include <cuda_bf16.h>
#include <cstdint>

// ---------------------------------------------------------------------------
// Plane_refine on sm_100 (no 'a' features): 2-layer pointwise MLP via
// bf16-split mma.sync (3 terms: hi*hi + hi*lo + lo*hi) + masked max-pool.
// Persistent kernel, 148 CTAs x 512 threads, 128-pt x 128-dim tiles.
// Warp (r = w&3, c = w>>2) owns the 32x32 output block (rows 32r.., cols 32c..).
// B operand ([n][k] k-contiguous = col-major KxN) is loaded with NON-trans
// ldmatrix: lane->n-row addressing yields the canonical b-fragment directly.
// ---------------------------------------------------------------------------

constexpr int N_PTS   = 131072;
constexpr int TILE_M  = 128;
constexpr int NTILES  = N_PTS / TILE_M;   // 1024
constexpr int GRID    = 148;
constexpr int THREADS = 512;
constexpr int P       = 64;

// smem byte offsets. Weight / A regions: rows of 128 bf16 = 256 B,
// 16B-chunk XOR swizzle: chunk' = chunk ^ (row & 7).
constexpr int OFF_W1HI = 0;
constexpr int OFF_W1LO = 32768;
constexpr int OFF_W2HI = 65536;
constexpr int OFF_W2LO = 98304;
constexpr int OFF_AHI  = 131072;   // feature/H1 hi; with ALO reused as f32 H2
constexpr int OFF_ALO  = 163840;
constexpr int OFF_MISC = 196608;
constexpr int OFF_B1   = OFF_MISC + 0;      // f32[128]
constexpr int OFF_B2   = OFF_MISC + 512;    // f32[128]
constexpr int OFF_PL   = OFF_MISC + 1024;   // f32[640]
constexpr int OFF_CTR  = OFF_MISC + 3584;   // f32[4]
constexpr int OFF_PMS  = OFF_MISC + 3600;   // u32[256]
constexpr int SMEM_BYTES = OFF_MISC + 4640; // 201,248 B

__device__ __forceinline__ uint32_t smem_u32(const void* p) {
    uint32_t a;
    asm("{ .reg .u64 t; cvta.to.shared.u64 t, %1; cvt.u32.u64 %0, t; }"
        : "=r"(a) : "l"(p));
    return a;
}

// byte address of 16B chunk `kc` (0..15) in row `row` of a swizzled region
__device__ __forceinline__ uint32_t swz(uint32_t region, int row, int kc) {
    return region + (uint32_t)(row * 256) + (uint32_t)((kc ^ (row & 7)) << 4);
}

__device__ __forceinline__ void split_bf16(float f, uint32_t& hi, uint32_t& lo) {
    __nv_bfloat16 h = __float2bfloat16_rn(f);
    float r = f - __bfloat162float(h);
    __nv_bfloat16 l = __float2bfloat16_rn(r);
    hi = (uint32_t)__bfloat16_as_ushort(h);
    lo = (uint32_t)__bfloat16_as_ushort(l);
}

#define LDSM_X4(r0, r1, r2, r3, a) \
    asm volatile("ldmatrix.sync.aligned.m8n8.x4.shared.b16 {%0,%1,%2,%3}, [%4];" \
                 : "=r"(r0), "=r"(r1), "=r"(r2), "=r"(r3) : "r"(a))
#define MMA16816(d, a0, a1, a2, a3, b0, b1) \
    asm volatile("mma.sync.aligned.m16n8k16.row.col.f32.bf16.bf16.f32 " \
                 "{%0,%1,%2,%3}, {%4,%5,%6,%7}, {%8,%9}, {%0,%1,%2,%3};" \
                 : "+f"((d)[0]), "+f"((d)[1]), "+f"((d)[2]), "+f"((d)[3]) \
                 : "r"(a0), "r"(a1), "r"(a2), "r"(a3), "r"(b0), "r"(b1))

// One 128x128x128 layer's worth of this warp's 32x32 block: 3 bf16 terms.
__device__ __forceinline__ void do_layer(uint32_t aHi, uint32_t aLo,
                                         uint32_t wHi, uint32_t wLo,
                                         float acc[2][4][4],
                                         int r, int c, int lane)
{
    const int arow  = 32 * r + (lane & 15);        // +16 for m-frag 1 (same &7)
    const int abit  = (lane >> 4) & 1;
    const int rs    = arow & 7;
    const uint32_t aoff = (uint32_t)(arow * 256);
    const int bn    = 32 * c + (lane & 7) + (((lane >> 4) & 1) << 3);
    const int bbit  = (lane >> 3) & 1;
    const int ns    = bn & 7;
    const uint32_t boff = (uint32_t)(bn * 256);

#pragma unroll
    for (int kk = 0; kk < 8; kk++) {
        const uint32_t kcA = (uint32_t)(((2 * kk + abit) ^ rs) << 4);
        const uint32_t kcB = (uint32_t)(((2 * kk + bbit) ^ ns) << 4);
        uint32_t ah[8], al[8], bh[8], bl[8];
        LDSM_X4(ah[0], ah[1], ah[2], ah[3], aHi + aoff + kcA);
        LDSM_X4(ah[4], ah[5], ah[6], ah[7], aHi + aoff + 4096 + kcA);
        LDSM_X4(al[0], al[1], al[2], al[3], aLo + aoff + kcA);
        LDSM_X4(al[4], al[5], al[6], al[7], aLo + aoff + 4096 + kcA);
        LDSM_X4(bh[0], bh[1], bh[2], bh[3], wHi + boff + kcB);
        LDSM_X4(bh[4], bh[5], bh[6], bh[7], wHi + boff + 4096 + kcB);
        LDSM_X4(bl[0], bl[1], bl[2], bl[3], wLo + boff + kcB);
        LDSM_X4(bl[4], bl[5], bl[6], bl[7], wLo + boff + 4096 + kcB);
#pragma unroll
        for (int i = 0; i < 2; i++) {
            const uint32_t* A = &ah[4 * i];
            const uint32_t* Al = &al[4 * i];
#pragma unroll
            for (int j = 0; j < 4; j++) {
                MMA16816(acc[i][j], A[0], A[1], A[2], A[3], bh[2 * j], bh[2 * j + 1]);
                MMA16816(acc[i][j], A[0], A[1], A[2], A[3], bl[2 * j], bl[2 * j + 1]);
                MMA16816(acc[i][j], Al[0], Al[1], Al[2], Al[3], bh[2 * j], bh[2 * j + 1]);
            }
        }
    }
}

__global__ void __launch_bounds__(THREADS, 1)
plane_refine_mma(const float* __restrict__ feature, const float* __restrict__ xyz,
                 const float* __restrict__ centers,
                 const float* __restrict__ plane_center, const float* __restrict__ plane_normal,
                 const float* __restrict__ plane_min, const float* __restrict__ plane_max,
                 const float* __restrict__ W1, const float* __restrict__ g1,
                 const float* __restrict__ b1,
                 const float* __restrict__ W2, const float* __restrict__ g2,
                 const float* __restrict__ b2,
                 float* __restrict__ out)
{
    extern __shared__ char smem[];
    const uint32_t sb = smem_u32(smem);

    float*    b1s = (float*)(smem + OFF_B1);
    float*    b2s = (float*)(smem + OFF_B2);
    float*    pl  = (float*)(smem + OFF_PL);
    float*    ctr = (float*)(smem + OFF_CTR);
    unsigned* pms = (unsigned*)(smem + OFF_PMS);
    float*    Hf  = (float*)(smem + OFF_AHI);   // f32 H2 view (64 KB, reuses A)

    const int tid  = threadIdx.x;
    const int lane = tid & 31;
    const int w    = tid >> 5;     // 0..15
    const int r    = w & 3;        // point-row block
    const int c    = w >> 2;       // dim-col block
    const int g    = lane >> 2;
    const int tig  = lane & 3;

    // ---- prologue: weights (fold g, split, swizzled), biases, plane constants
    for (int idx = tid; idx < 16384; idx += THREADS) {
        const int o = idx >> 7, k = idx & 127;
        const uint32_t a1 = swz(OFF_W1HI, o, k >> 3) + (uint32_t)((k & 7) * 2);
        uint32_t h, l;
        split_bf16(W1[idx] * g1[o], h, l);
        *(unsigned short*)(smem + a1)         = (unsigned short)h;
        *(unsigned short*)(smem + a1 + 32768) = (unsigned short)l;
        split_bf16(W2[idx] * g2[o], h, l);
        *(unsigned short*)(smem + a1 + 65536) = (unsigned short)h;
        *(unsigned short*)(smem + a1 + 98304) = (unsigned short)l;
    }
    if (tid < 128) { b1s[tid] = b1[tid]; b2s[tid] = b2[tid]; }
    if (tid < P) {
        const float nx = plane_normal[tid * 3 + 0];
        const float ny = plane_normal[tid * 3 + 1];
        const float nz = plane_normal[tid * 3 + 2];
        pl[tid]       = nx;  pl[64 + tid]  = ny;  pl[128 + tid] = nz;
        pl[192 + tid] = plane_center[tid * 3 + 0] * nx
                      + plane_center[tid * 3 + 1] * ny
                      + plane_center[tid * 3 + 2] * nz;
        pl[256 + tid] = plane_min[tid * 3 + 0];
        pl[320 + tid] = plane_min[tid * 3 + 1];
        pl[384 + tid] = plane_min[tid * 3 + 2];
        pl[448 + tid] = plane_max[tid * 3 + 0];
        pl[512 + tid] = plane_max[tid * 3 + 1];
        pl[576 + tid] = plane_max[tid * 3 + 2];
    }
    if (tid < 3) ctr[tid] = centers[tid];
    __syncthreads();

    const float cx = ctr[0], cy = ctr[1], cz = ctr[2];

    float4 poolv[4];
#pragma unroll
    for (int j = 0; j < 4; j++) poolv[j] = make_float4(0.f, 0.f, 0.f, 0.f);

    for (int t = blockIdx.x; t < NTILES; t += GRID) {
        const int base = t * TILE_M;
        __syncthreads();   // pool of previous tile done reading Hf (A region)

        // ---- load feature tile, split to Ahi/Alo
        {
            const float4* src = (const float4*)(feature + (size_t)base * 128);
#pragma unroll
            for (int jj = 0; jj < 8; jj++) {
                const int idx = tid + jj * THREADS;      // 4096 float4
                const int pt  = idx >> 5, k4 = idx & 31; // k0 = 4*k4
                const float4 f = src[idx];
                uint32_t h0, l0, h1, l1, h2, l2, h3, l3;
                split_bf16(f.x, h0, l0); split_bf16(f.y, h1, l1);
                split_bf16(f.z, h2, l2); split_bf16(f.w, h3, l3);
                const uint32_t a = swz(OFF_AHI, pt, k4 >> 1) + (uint32_t)((k4 & 1) * 8);
                *(uint2*)(smem + a)         = make_uint2(h0 | (h1 << 16), h2 | (h3 << 16));
                *(uint2*)(smem + a + 32768) = make_uint2(l0 | (l1 << 16), l2 | (l3 << 16));
            }
        }

        // ---- masks: lane <-> point within each 32-pt half, warp w -> planes 4w..
#pragma unroll
        for (int h = 0; h < 4; h++) {
            const int pt = base + 32 * h + lane;
            const float px = xyz[(size_t)pt * 3 + 0] + cx;
            const float py = xyz[(size_t)pt * 3 + 1] + cy;
            const float pz = xyz[(size_t)pt * 3 + 2] + cz;
#pragma unroll
            for (int j = 0; j < 4; j++) {
                const int p = 4 * w + j;
                const float d = fabsf(px * pl[p] + py * pl[64 + p] + pz * pl[128 + p]
                                      - pl[192 + p]);
                bool ok = d < 0.05f;
                float mn, mx;
                mn = pl[256 + p]; mx = pl[448 + p];
                ok = ok && ((px >= mn && px < mx) || (mx == 0.f));
                mn = pl[320 + p]; mx = pl[512 + p];
                ok = ok && ((py >= mn && py < mx) || (mx == 0.f));
                mn = pl[384 + p]; mx = pl[576 + p];
                ok = ok && ((pz >= mn && pz < mx) || (mx == 0.f));
                const unsigned bal = __ballot_sync(0xffffffffu, ok);
                if (lane == 0) pms[p * 4 + h] = bal;
            }
        }
        __syncthreads();

        // ---- layer 1 ----
        float acc[2][4][4];
#pragma unroll
        for (int i = 0; i < 2; i++)
#pragma unroll
            for (int j = 0; j < 4; j++)
#pragma unroll
                for (int q = 0; q < 4; q++) acc[i][j][q] = 0.f;

        do_layer(sb + OFF_AHI, sb + OFF_ALO, sb + OFF_W1HI, sb + OFF_W1LO,
                 acc, r, c, lane);
        __syncthreads();   // everyone done reading feature splits

        // ---- epilogue 1: +b1, relu, split back into Ahi/Alo
#pragma unroll
        for (int i = 0; i < 2; i++)
#pragma unroll
            for (int h = 0; h < 2; h++) {
                const int row = 32 * r + 16 * i + 8 * h + g;
#pragma unroll
                for (int j = 0; j < 4; j++) {
                    const int col0 = 32 * c + 8 * j + 2 * tig;
                    const float2 bb = *(const float2*)&b1s[col0];
                    const float v0 = fmaxf(acc[i][j][2 * h + 0] + bb.x, 0.f);
                    const float v1 = fmaxf(acc[i][j][2 * h + 1] + bb.y, 0.f);
                    uint32_t h0, l0, h1, l1;
                    split_bf16(v0, h0, l0); split_bf16(v1, h1, l1);
                    const uint32_t a = swz(OFF_AHI, row, 4 * c + j) + (uint32_t)(4 * tig);
                    *(uint32_t*)(smem + a)         = h0 | (h1 << 16);
                    *(uint32_t*)(smem + a + 32768) = l0 | (l1 << 16);
                }
            }
        __syncthreads();

        // ---- layer 2 ----
#pragma unroll
        for (int i = 0; i < 2; i++)
#pragma unroll
            for (int j = 0; j < 4; j++)
#pragma unroll
                for (int q = 0; q < 4; q++) acc[i][j][q] = 0.f;

        do_layer(sb + OFF_AHI, sb + OFF_ALO, sb + OFF_W2HI, sb + OFF_W2LO,
                 acc, r, c, lane);
        __syncthreads();   // everyone done reading H1 splits

        // ---- epilogue 2: +b2, relu, f32 into Hf (16B-chunk xor swizzle)
#pragma unroll
        for (int i = 0; i < 2; i++)
#pragma unroll
            for (int h = 0; h < 2; h++) {
                const int row = 32 * r + 16 * i + 8 * h + g;
                const int rsw = (row & 7) << 1;
#pragma unroll
                for (int j = 0; j < 4; j++) {
                    const int col0 = 32 * c + 8 * j + 2 * tig;
                    const float2 bb = *(const float2*)&b2s[col0];
                    float2 v;
                    v.x = fmaxf(acc[i][j][2 * h + 0] + bb.x, 0.f);
                    v.y = fmaxf(acc[i][j][2 * h + 1] + bb.y, 0.f);
                    const int ch = 2 * (4 * c + j) + (tig >> 1);
                    const uint32_t off = (uint32_t)(row * 512 + ((ch ^ rsw) << 4)
                                                    + (tig & 1) * 8);
                    *(float2*)((char*)Hf + off) = v;
                }
            }
        __syncthreads();

        // ---- pool: warp owns planes 4w..4w+3, lane owns dims 4lane..4lane+3
#pragma unroll
        for (int j = 0; j < 4; j++) {
            const int p = 4 * w + j;
#pragma unroll
            for (int h = 0; h < 4; h++) {
                unsigned bits = pms[p * 4 + h];
                while (bits) {
                    const int i = __ffs(bits) - 1;
                    bits &= bits - 1;
                    const int pt = 32 * h + i;
                    const float4 v = *(const float4*)
                        &Hf[pt * 128 + ((lane ^ ((pt & 7) << 1)) << 2)];
                    poolv[j].x = fmaxf(poolv[j].x, v.x);
                    poolv[j].y = fmaxf(poolv[j].y, v.y);
                    poolv[j].z = fmaxf(poolv[j].z, v.z);
                    poolv[j].w = fmaxf(poolv[j].w, v.w);
                }
            }
        }
    }

    // ---- merge (nonneg float max == uint max on float bits)
    {
        unsigned* o32 = (unsigned*)out;
#pragma unroll
        for (int j = 0; j < 4; j++) {
            const int p = 4 * w + j;
            const int bidx = p * 128 + lane * 4;
            atomicMax(&o32[bidx + 0], __float_as_uint(poolv[j].x));
            atomicMax(&o32[bidx + 1], __float_as_uint(poolv[j].y));
            atomicMax(&o32[bidx + 2], __float_as_uint(poolv[j].z));
            atomicMax(&o32[bidx + 3], __float_as_uint(poolv[j].w));
        }
    }
}

__global__ void zero_out_kernel(float* __restrict__ out, int n) {
    const int i = blockIdx.x * blockDim.x + threadIdx.x;
    if (i < n) out[i] = 0.f;
}

extern "C" void kernel_launch(void* const* d_in, const int* in_sizes, int n_in,
                              void* d_out, int out_size)
{
    const float* feature      = (const float*)d_in[0];
    const float* xyz          = (const float*)d_in[1];
    const float* centers      = (const float*)d_in[2];
    const float* plane_center = (const float*)d_in[3];
    const float* plane_normal = (const float*)d_in[4];
    const float* plane_min    = (const float*)d_in[5];
    const float* plane_max    = (const float*)d_in[6];
    const float* W1           = (const float*)d_in[7];
    const float* g1           = (const float*)d_in[8];
    const float* b1           = (const float*)d_in[9];
    const float* W2           = (const float*)d_in[10];
    const float* g2           = (const float*)d_in[11];
    const float* b2           = (const float*)d_in[12];
    float* out = (float*)d_out;

    cudaFuncSetAttribute(plane_refine_mma,
                         cudaFuncAttributeMaxDynamicSharedMemorySize, SMEM_BYTES);

    zero_out_kernel<<<(P * 128 + 255) / 256, 256>>>(out, P * 128);
    plane_refine_mma<<<GRID, THREADS, SMEM_BYTES>>>(
        feature, xyz, centers, plane_center, plane_normal, plane_min, plane_max,
        W1, g1, b1, W2, g2, b2, out);
}

// round 6
// speedup vs baseline: 3.2490x; 1.0270x over previous
#include <cuda_runtime.h>
#include <cuda_bf16.h>
#include <cstdint>

// ---------------------------------------------------------------------------
// Plane_refine on sm_100: 2-layer pointwise MLP via bf16-split mma.sync
// (3 terms: hi*hi + hi*lo + lo*hi) + masked max-pool.
// Persistent kernel, 148 CTAs x 512 threads, PING-PONG: two independent
// 256-thread groups, each processing the 64-point half of each 128-pt tile
// with group-local buffers and named barriers, so one group's MMAs hide the
// other group's loads/epilogues/barriers.
// ---------------------------------------------------------------------------

constexpr int N_PTS   = 131072;
constexpr int TILE_M  = 128;    // per CTA-iteration; 64 per group
constexpr int NTILES  = N_PTS / TILE_M;   // 1024
constexpr int GRID    = 148;
constexpr int THREADS = 512;
constexpr int P       = 64;

// smem byte offsets. Weight rows: 128 bf16 = 256 B, 16B-chunk XOR swizzle
// chunk' = chunk ^ (row & 7).
constexpr int OFF_W1HI = 0;
constexpr int OFF_W1LO = 32768;
constexpr int OFF_W2HI = 65536;
constexpr int OFF_W2LO = 98304;
// group A regions: 64 rows x 256B = 16 KB each (hi, lo); Hf f32 reuses hi+lo
constexpr int OFF_A0HI = 131072;
constexpr int OFF_A0LO = 147456;
constexpr int OFF_A1HI = 163840;
constexpr int OFF_A1LO = 180224;
constexpr int OFF_MISC = 196608;
constexpr int OFF_B1   = OFF_MISC + 0;      // f32[128]
constexpr int OFF_B2   = OFF_MISC + 512;    // f32[128]
constexpr int OFF_PL   = OFF_MISC + 1024;   // f32[640]
constexpr int OFF_CTR  = OFF_MISC + 3584;   // f32[4]
constexpr int OFF_PMS  = OFF_MISC + 3600;   // u32[2][64][2] = 1024 B
constexpr int SMEM_BYTES = OFF_MISC + 4640;

__device__ __forceinline__ uint32_t smem_u32(const void* p) {
    uint32_t a;
    asm("{ .reg .u64 t; cvta.to.shared.u64 t, %1; cvt.u32.u64 %0, t; }"
        : "=r"(a) : "l"(p));
    return a;
}

// byte address of 16B chunk `kc` (0..15) in row `row` of a swizzled region
__device__ __forceinline__ uint32_t swz(uint32_t region, int row, int kc) {
    return region + (uint32_t)(row * 256) + (uint32_t)((kc ^ (row & 7)) << 4);
}

__device__ __forceinline__ void split_bf16(float f, uint32_t& hi, uint32_t& lo) {
    __nv_bfloat16 h = __float2bfloat16_rn(f);
    float r = f - __bfloat162float(h);
    __nv_bfloat16 l = __float2bfloat16_rn(r);
    hi = (uint32_t)__bfloat16_as_ushort(h);
    lo = (uint32_t)__bfloat16_as_ushort(l);
}

#define LDSM_X4(r0, r1, r2, r3, a) \
    asm volatile("ldmatrix.sync.aligned.m8n8.x4.shared.b16 {%0,%1,%2,%3}, [%4];" \
                 : "=r"(r0), "=r"(r1), "=r"(r2), "=r"(r3) : "r"(a))
#define MMA16816(d, a0, a1, a2, a3, b0, b1) \
    asm volatile("mma.sync.aligned.m16n8k16.row.col.f32.bf16.bf16.f32 " \
                 "{%0,%1,%2,%3}, {%4,%5,%6,%7}, {%8,%9}, {%0,%1,%2,%3};" \
                 : "+f"((d)[0]), "+f"((d)[1]), "+f"((d)[2]), "+f"((d)[3]) \
                 : "r"(a0), "r"(a1), "r"(a2), "r"(a3), "r"(b0), "r"(b1))
#define GBAR(id) asm volatile("bar.sync %0, 256;" :: "r"(id) : "memory")

// One 64x128x128 layer for this warp's 32x32 block: 3 bf16 terms.
__device__ __forceinline__ void do_layer(uint32_t aHi, uint32_t aLo,
                                         uint32_t wHi, uint32_t wLo,
                                         float acc[2][4][4],
                                         int r2, int c2, int lane)
{
    const int arow  = 32 * r2 + (lane & 15);
    const int abit  = (lane >> 4) & 1;
    const int rs    = arow & 7;
    const uint32_t aoff = (uint32_t)(arow * 256);
    const int bn    = 32 * c2 + (lane & 7) + (((lane >> 4) & 1) << 3);
    const int bbit  = (lane >> 3) & 1;
    const int ns    = bn & 7;
    const uint32_t boff = (uint32_t)(bn * 256);

#pragma unroll
    for (int kk = 0; kk < 8; kk++) {
        const uint32_t kcA = (uint32_t)(((2 * kk + abit) ^ rs) << 4);
        const uint32_t kcB = (uint32_t)(((2 * kk + bbit) ^ ns) << 4);
        uint32_t ah[8], al[8], bh[8], bl[8];
        LDSM_X4(ah[0], ah[1], ah[2], ah[3], aHi + aoff + kcA);
        LDSM_X4(ah[4], ah[5], ah[6], ah[7], aHi + aoff + 4096 + kcA);
        LDSM_X4(al[0], al[1], al[2], al[3], aLo + aoff + kcA);
        LDSM_X4(al[4], al[5], al[6], al[7], aLo + aoff + 4096 + kcA);
        LDSM_X4(bh[0], bh[1], bh[2], bh[3], wHi + boff + kcB);
        LDSM_X4(bh[4], bh[5], bh[6], bh[7], wHi + boff + 4096 + kcB);
        LDSM_X4(bl[0], bl[1], bl[2], bl[3], wLo + boff + kcB);
        LDSM_X4(bl[4], bl[5], bl[6], bl[7], wLo + boff + 4096 + kcB);
#pragma unroll
        for (int i = 0; i < 2; i++) {
            const uint32_t* A  = &ah[4 * i];
            const uint32_t* Al = &al[4 * i];
#pragma unroll
            for (int j = 0; j < 4; j++) {
                MMA16816(acc[i][j], A[0], A[1], A[2], A[3], bh[2 * j], bh[2 * j + 1]);
                MMA16816(acc[i][j], A[0], A[1], A[2], A[3], bl[2 * j], bl[2 * j + 1]);
                MMA16816(acc[i][j], Al[0], Al[1], Al[2], Al[3], bh[2 * j], bh[2 * j + 1]);
            }
        }
    }
}

__global__ void __launch_bounds__(THREADS, 1)
plane_refine_pp(const float* __restrict__ feature, const float* __restrict__ xyz,
                const float* __restrict__ centers,
                const float* __restrict__ plane_center, const float* __restrict__ plane_normal,
                const float* __restrict__ plane_min, const float* __restrict__ plane_max,
                const float* __restrict__ W1, const float* __restrict__ g1,
                const float* __restrict__ b1,
                const float* __restrict__ W2, const float* __restrict__ g2,
                const float* __restrict__ b2,
                float* __restrict__ out)
{
    extern __shared__ char smem[];
    const uint32_t sb = smem_u32(smem);

    float*    b1s = (float*)(smem + OFF_B1);
    float*    b2s = (float*)(smem + OFF_B2);
    float*    pl  = (float*)(smem + OFF_PL);
    float*    ctr = (float*)(smem + OFF_CTR);
    unsigned* pms = (unsigned*)(smem + OFF_PMS);   // [2][64][2]

    const int tid  = threadIdx.x;
    const int lane = tid & 31;
    const int w    = tid >> 5;          // 0..15
    const int grp  = w >> 3;            // 0 / 1
    const int wg   = w & 7;             // warp within group
    const int r2   = wg & 1;            // row block (of 2) in 64-pt half
    const int c2   = wg >> 1;           // col block (of 4)
    const int g    = lane >> 2;
    const int tig  = lane & 3;
    const int gtid = tid & 255;         // thread within group
    const int barid = grp + 1;

    const uint32_t aHi = sb + (grp ? OFF_A1HI : OFF_A0HI);
    const uint32_t aLo = sb + (grp ? OFF_A1LO : OFF_A0LO);
    float* Hf = (float*)(smem + (grp ? OFF_A1HI : OFF_A0HI));  // 32 KB f32 view
    unsigned* pmg = pms + grp * 128;    // [64][2]

    // ---- prologue (whole CTA): weights (fold g, split, swizzled), consts
    for (int idx = tid; idx < 16384; idx += THREADS) {
        const int o = idx >> 7, k = idx & 127;
        const uint32_t a1 = swz(0, o, k >> 3) + (uint32_t)((k & 7) * 2);
        uint32_t h, l;
        split_bf16(W1[idx] * g1[o], h, l);
        *(unsigned short*)(smem + a1 + OFF_W1HI) = (unsigned short)h;
        *(unsigned short*)(smem + a1 + OFF_W1LO) = (unsigned short)l;
        split_bf16(W2[idx] * g2[o], h, l);
        *(unsigned short*)(smem + a1 + OFF_W2HI) = (unsigned short)h;
        *(unsigned short*)(smem + a1 + OFF_W2LO) = (unsigned short)l;
    }
    if (tid < 128) { b1s[tid] = b1[tid]; b2s[tid] = b2[tid]; }
    if (tid < P) {
        const float nx = plane_normal[tid * 3 + 0];
        const float ny = plane_normal[tid * 3 + 1];
        const float nz = plane_normal[tid * 3 + 2];
        pl[tid]       = nx;  pl[64 + tid]  = ny;  pl[128 + tid] = nz;
        pl[192 + tid] = plane_center[tid * 3 + 0] * nx
                      + plane_center[tid * 3 + 1] * ny
                      + plane_center[tid * 3 + 2] * nz;
        pl[256 + tid] = plane_min[tid * 3 + 0];
        pl[320 + tid] = plane_min[tid * 3 + 1];
        pl[384 + tid] = plane_min[tid * 3 + 2];
        pl[448 + tid] = plane_max[tid * 3 + 0];
        pl[512 + tid] = plane_max[tid * 3 + 1];
        pl[576 + tid] = plane_max[tid * 3 + 2];
    }
    if (tid < 3) ctr[tid] = centers[tid];
    __syncthreads();   // last CTA-wide barrier; groups diverge after this

    const float cx = ctr[0], cy = ctr[1], cz = ctr[2];

    // warp owns planes 8*wg .. 8*wg+7 over its group's points; lane: dims 4lane..
    float4 poolv[8];
#pragma unroll
    for (int j = 0; j < 8; j++) poolv[j] = make_float4(0.f, 0.f, 0.f, 0.f);

    for (int t = blockIdx.x; t < NTILES; t += GRID) {
        const int gbase = t * TILE_M + 64 * grp;
        GBAR(barid);   // prev tile's pool reads of Hf done

        // ---- load 64-pt feature half, split to aHi/aLo
        {
            const float4* src = (const float4*)(feature + (size_t)gbase * 128);
#pragma unroll
            for (int jj = 0; jj < 8; jj++) {
                const int idx = gtid + jj * 256;         // 2048 float4
                const int pt  = idx >> 5, k4 = idx & 31; // k0 = 4*k4
                const float4 f = src[idx];
                uint32_t h0, l0, h1, l1, h2, l2, h3, l3;
                split_bf16(f.x, h0, l0); split_bf16(f.y, h1, l1);
                split_bf16(f.z, h2, l2); split_bf16(f.w, h3, l3);
                const uint32_t a = swz(0, pt, k4 >> 1) + (uint32_t)((k4 & 1) * 8);
                *(uint2*)(smem + (aHi - sb) + a) = make_uint2(h0 | (h1 << 16), h2 | (h3 << 16));
                *(uint2*)(smem + (aLo - sb) + a) = make_uint2(l0 | (l1 << 16), l2 | (l3 << 16));
            }
        }

        // ---- masks: warp computes its 8 planes for both 32-pt chunks
#pragma unroll
        for (int h = 0; h < 2; h++) {
            const int pt = gbase + 32 * h + lane;
            const float px = xyz[(size_t)pt * 3 + 0] + cx;
            const float py = xyz[(size_t)pt * 3 + 1] + cy;
            const float pz = xyz[(size_t)pt * 3 + 2] + cz;
#pragma unroll
            for (int j = 0; j < 8; j++) {
                const int p = 8 * wg + j;
                const float d = fabsf(px * pl[p] + py * pl[64 + p] + pz * pl[128 + p]
                                      - pl[192 + p]);
                bool ok = d < 0.05f;
                float mn, mx;
                mn = pl[256 + p]; mx = pl[448 + p];
                ok = ok && ((px >= mn && px < mx) || (mx == 0.f));
                mn = pl[320 + p]; mx = pl[512 + p];
                ok = ok && ((py >= mn && py < mx) || (mx == 0.f));
                mn = pl[384 + p]; mx = pl[576 + p];
                ok = ok && ((pz >= mn && pz < mx) || (mx == 0.f));
                const unsigned bal = __ballot_sync(0xffffffffu, ok);
                if (lane == 0) pmg[p * 2 + h] = bal;
            }
        }
        GBAR(barid);

        // ---- layer 1 ----
        float acc[2][4][4];
#pragma unroll
        for (int i = 0; i < 2; i++)
#pragma unroll
            for (int j = 0; j < 4; j++)
#pragma unroll
                for (int q = 0; q < 4; q++) acc[i][j][q] = 0.f;

        do_layer(aHi, aLo, sb + OFF_W1HI, sb + OFF_W1LO, acc, r2, c2, lane);
        GBAR(barid);   // group done reading feature splits

        // ---- epilogue 1: +b1, relu, split back into aHi/aLo
#pragma unroll
        for (int i = 0; i < 2; i++)
#pragma unroll
            for (int h = 0; h < 2; h++) {
                const int row = 32 * r2 + 16 * i + 8 * h + g;
#pragma unroll
                for (int j = 0; j < 4; j++) {
                    const int col0 = 32 * c2 + 8 * j + 2 * tig;
                    const float2 bb = *(const float2*)&b1s[col0];
                    const float v0 = fmaxf(acc[i][j][2 * h + 0] + bb.x, 0.f);
                    const float v1 = fmaxf(acc[i][j][2 * h + 1] + bb.y, 0.f);
                    uint32_t h0, l0, h1, l1;
                    split_bf16(v0, h0, l0); split_bf16(v1, h1, l1);
                    const uint32_t a = swz(0, row, 4 * c2 + j) + (uint32_t)(4 * tig);
                    *(uint32_t*)(smem + (aHi - sb) + a) = h0 | (h1 << 16);
                    *(uint32_t*)(smem + (aLo - sb) + a) = l0 | (l1 << 16);
                }
            }
        GBAR(barid);

        // ---- layer 2 ----
#pragma unroll
        for (int i = 0; i < 2; i++)
#pragma unroll
            for (int j = 0; j < 4; j++)
#pragma unroll
                for (int q = 0; q < 4; q++) acc[i][j][q] = 0.f;

        do_layer(aHi, aLo, sb + OFF_W2HI, sb + OFF_W2LO, acc, r2, c2, lane);
        GBAR(barid);   // group done reading H1 splits

        // ---- epilogue 2: +b2, relu, f32 into Hf (16B-chunk xor swizzle)
#pragma unroll
        for (int i = 0; i < 2; i++)
#pragma unroll
            for (int h = 0; h < 2; h++) {
                const int row = 32 * r2 + 16 * i + 8 * h + g;
                const int rsw = (row & 7) << 1;
#pragma unroll
                for (int j = 0; j < 4; j++) {
                    const int col0 = 32 * c2 + 8 * j + 2 * tig;
                    const float2 bb = *(const float2*)&b2s[col0];
                    float2 v;
                    v.x = fmaxf(acc[i][j][2 * h + 0] + bb.x, 0.f);
                    v.y = fmaxf(acc[i][j][2 * h + 1] + bb.y, 0.f);
                    const int ch = 2 * (4 * c2 + j) + (tig >> 1);
                    const uint32_t off = (uint32_t)(row * 512 + ((ch ^ rsw) << 4)
                                                    + (tig & 1) * 8);
                    *(float2*)((char*)Hf + off) = v;
                }
            }
        GBAR(barid);

        // ---- pool: warp's 8 planes over this group's 64 points
#pragma unroll
        for (int j = 0; j < 8; j++) {
            const int p = 8 * wg + j;
#pragma unroll
            for (int h = 0; h < 2; h++) {
                unsigned bits = pmg[p * 2 + h];
                while (bits) {
                    const int i = __ffs(bits) - 1;
                    bits &= bits - 1;
                    const int pt = 32 * h + i;
                    const float4 v = *(const float4*)
                        &Hf[pt * 128 + ((lane ^ ((pt & 7) << 1)) << 2)];
                    poolv[j].x = fmaxf(poolv[j].x, v.x);
                    poolv[j].y = fmaxf(poolv[j].y, v.y);
                    poolv[j].z = fmaxf(poolv[j].z, v.z);
                    poolv[j].w = fmaxf(poolv[j].w, v.w);
                }
            }
        }
    }

    // ---- merge (nonneg float max == uint max on float bits)
    {
        unsigned* o32 = (unsigned*)out;
#pragma unroll
        for (int j = 0; j < 8; j++) {
            const int p = 8 * wg + j;
            const int bidx = p * 128 + lane * 4;
            atomicMax(&o32[bidx + 0], __float_as_uint(poolv[j].x));
            atomicMax(&o32[bidx + 1], __float_as_uint(poolv[j].y));
            atomicMax(&o32[bidx + 2], __float_as_uint(poolv[j].z));
            atomicMax(&o32[bidx + 3], __float_as_uint(poolv[j].w));
        }
    }
}

__global__ void zero_out_kernel(float* __restrict__ out, int n) {
    const int i = blockIdx.x * blockDim.x + threadIdx.x;
    if (i < n) out[i] = 0.f;
}

extern "C" void kernel_launch(void* const* d_in, const int* in_sizes, int n_in,
                              void* d_out, int out_size)
{
    const float* feature      = (const float*)d_in[0];
    const float* xyz          = (const float*)d_in[1];
    const float* centers      = (const float*)d_in[2];
    const float* plane_center = (const float*)d_in[3];
    const float* plane_normal = (const float*)d_in[4];
    const float* plane_min    = (const float*)d_in[5];
    const float* plane_max    = (const float*)d_in[6];
    const float* W1           = (const float*)d_in[7];
    const float* g1           = (const float*)d_in[8];
    const float* b1           = (const float*)d_in[9];
    const float* W2           = (const float*)d_in[10];
    const float* g2           = (const float*)d_in[11];
    const float* b2           = (const float*)d_in[12];
    float* out = (float*)d_out;

    cudaFuncSetAttribute(plane_refine_pp,
                         cudaFuncAttributeMaxDynamicSharedMemorySize, SMEM_BYTES);

    zero_out_kernel<<<(P * 128 + 255) / 256, 256>>>(out, P * 128);
    plane_refine_pp<<<GRID, THREADS, SMEM_BYTES>>>(
        feature, xyz, centers, plane_center, plane_normal, plane_min, plane_max,
        W1, g1, b1, W2, g2, b2, out);
}

// round 7
// speedup vs baseline: 4.4897x; 1.3819x over previous
#include <cuda_runtime.h>
#include <cuda_fp16.h>
#include <cstdint>

// ---------------------------------------------------------------------------
// Plane_refine on sm_100: 2-layer pointwise MLP via fp16 mma.sync (single
// term, f32 accumulate) + masked max-pool. Persistent kernel, 148 CTAs x 512
// threads, two 256-thread groups each handling the 64-pt half of each tile.
// ---------------------------------------------------------------------------

constexpr int N_PTS   = 131072;
constexpr int TILE_M  = 128;
constexpr int NTILES  = N_PTS / TILE_M;   // 1024
constexpr int GRID    = 148;
constexpr int THREADS = 512;
constexpr int P       = 64;

// smem byte offsets. f16 rows: 128 f16 = 256 B, 16B-chunk XOR swizzle
// chunk' = chunk ^ (row & 7).
constexpr int OFF_W1  = 0;          // 32 KB
constexpr int OFF_W2  = 32768;      // 32 KB
constexpr int OFF_A0  = 65536;      // 16 KB (64 rows x 256B)
constexpr int OFF_A1  = 81920;      // 16 KB
constexpr int OFF_H0  = 98304;      // 32 KB f32 (64 rows x 512B)
constexpr int OFF_H1  = 131072;     // 32 KB
constexpr int OFF_MISC = 163840;
constexpr int OFF_B1   = OFF_MISC + 0;      // f32[128]
constexpr int OFF_B2   = OFF_MISC + 512;    // f32[128]
constexpr int OFF_PL   = OFF_MISC + 1024;   // f32[640]
constexpr int OFF_CTR  = OFF_MISC + 3584;   // f32[4]
constexpr int OFF_PMS  = OFF_MISC + 3600;   // u32[2][64][2]
constexpr int SMEM_BYTES = OFF_MISC + 4640; // 168,480 B

__device__ __forceinline__ uint32_t smem_u32(const void* p) {
    uint32_t a;
    asm("{ .reg .u64 t; cvta.to.shared.u64 t, %1; cvt.u32.u64 %0, t; }"
        : "=r"(a) : "l"(p));
    return a;
}

// byte address of 16B chunk `kc` (0..15) in row `row` of a swizzled f16 region
__device__ __forceinline__ uint32_t swz(uint32_t region, int row, int kc) {
    return region + (uint32_t)(row * 256) + (uint32_t)((kc ^ (row & 7)) << 4);
}

__device__ __forceinline__ uint32_t pack_h2(float a, float b) {
    __half2 h = __floats2half2_rn(a, b);   // a -> low 16 bits
    return *(uint32_t*)&h;
}

#define LDSM_X4(r0, r1, r2, r3, a) \
    asm volatile("ldmatrix.sync.aligned.m8n8.x4.shared.b16 {%0,%1,%2,%3}, [%4];" \
                 : "=r"(r0), "=r"(r1), "=r"(r2), "=r"(r3) : "r"(a))
#define MMA16816(d, a0, a1, a2, a3, b0, b1) \
    asm volatile("mma.sync.aligned.m16n8k16.row.col.f32.f16.f16.f32 " \
                 "{%0,%1,%2,%3}, {%4,%5,%6,%7}, {%8,%9}, {%0,%1,%2,%3};" \
                 : "+f"((d)[0]), "+f"((d)[1]), "+f"((d)[2]), "+f"((d)[3]) \
                 : "r"(a0), "r"(a1), "r"(a2), "r"(a3), "r"(b0), "r"(b1))
#define GBAR(id) asm volatile("bar.sync %0, 256;" :: "r"(id) : "memory")

// One 64x128x128 layer for this warp's 32x32 block (single fp16 term).
__device__ __forceinline__ void do_layer(uint32_t aB, uint32_t wB,
                                         float acc[2][4][4],
                                         int r2, int c2, int lane)
{
    const int arow  = 32 * r2 + (lane & 15);
    const int abit  = (lane >> 4) & 1;
    const int rs    = arow & 7;
    const uint32_t aoff = (uint32_t)(arow * 256);
    const int bn    = 32 * c2 + (lane & 7) + (((lane >> 4) & 1) << 3);
    const int bbit  = (lane >> 3) & 1;
    const int ns    = bn & 7;
    const uint32_t boff = (uint32_t)(bn * 256);

#pragma unroll
    for (int kk = 0; kk < 8; kk++) {
        const uint32_t kcA = (uint32_t)(((2 * kk + abit) ^ rs) << 4);
        const uint32_t kcB = (uint32_t)(((2 * kk + bbit) ^ ns) << 4);
        uint32_t a[8], b[8];
        LDSM_X4(a[0], a[1], a[2], a[3], aB + aoff + kcA);
        LDSM_X4(a[4], a[5], a[6], a[7], aB + aoff + 4096 + kcA);
        LDSM_X4(b[0], b[1], b[2], b[3], wB + boff + kcB);
        LDSM_X4(b[4], b[5], b[6], b[7], wB + boff + 4096 + kcB);
#pragma unroll
        for (int i = 0; i < 2; i++) {
            const uint32_t* A = &a[4 * i];
#pragma unroll
            for (int j = 0; j < 4; j++)
                MMA16816(acc[i][j], A[0], A[1], A[2], A[3], b[2 * j], b[2 * j + 1]);
        }
    }
}

__global__ void __launch_bounds__(THREADS, 1)
plane_refine_h(const float* __restrict__ feature, const float* __restrict__ xyz,
               const float* __restrict__ centers,
               const float* __restrict__ plane_center, const float* __restrict__ plane_normal,
               const float* __restrict__ plane_min, const float* __restrict__ plane_max,
               const float* __restrict__ W1, const float* __restrict__ g1,
               const float* __restrict__ b1,
               const float* __restrict__ W2, const float* __restrict__ g2,
               const float* __restrict__ b2,
               float* __restrict__ out)
{
    extern __shared__ char smem[];
    const uint32_t sb = smem_u32(smem);

    float*    b1s = (float*)(smem + OFF_B1);
    float*    b2s = (float*)(smem + OFF_B2);
    float*    pl  = (float*)(smem + OFF_PL);
    float*    ctr = (float*)(smem + OFF_CTR);
    unsigned* pms = (unsigned*)(smem + OFF_PMS);

    const int tid  = threadIdx.x;
    const int lane = tid & 31;
    const int w    = tid >> 5;
    const int grp  = w >> 3;
    const int wg   = w & 7;
    const int r2   = wg & 1;
    const int c2   = wg >> 1;
    const int g    = lane >> 2;
    const int tig  = lane & 3;
    const int gtid = tid & 255;
    const int barid = grp + 1;

    const uint32_t aB = sb + (grp ? OFF_A1 : OFF_A0);
    float* Hf = (float*)(smem + (grp ? OFF_H1 : OFF_H0));
    unsigned* pmg = pms + grp * 128;

    // ---- prologue: weights (fold g, -> f16, swizzled), consts
    for (int idx = tid; idx < 16384; idx += THREADS) {
        const int o = idx >> 7, k = idx & 127;
        const uint32_t a1 = swz(0, o, k >> 3) + (uint32_t)((k & 7) * 2);
        __half h1v = __float2half_rn(W1[idx] * g1[o]);
        __half h2v = __float2half_rn(W2[idx] * g2[o]);
        *(__half*)(smem + a1 + OFF_W1) = h1v;
        *(__half*)(smem + a1 + OFF_W2) = h2v;
    }
    if (tid < 128) { b1s[tid] = b1[tid]; b2s[tid] = b2[tid]; }
    if (tid < P) {
        const float nx = plane_normal[tid * 3 + 0];
        const float ny = plane_normal[tid * 3 + 1];
        const float nz = plane_normal[tid * 3 + 2];
        pl[tid]       = nx;  pl[64 + tid]  = ny;  pl[128 + tid] = nz;
        pl[192 + tid] = plane_center[tid * 3 + 0] * nx
                      + plane_center[tid * 3 + 1] * ny
                      + plane_center[tid * 3 + 2] * nz;
        pl[256 + tid] = plane_min[tid * 3 + 0];
        pl[320 + tid] = plane_min[tid * 3 + 1];
        pl[384 + tid] = plane_min[tid * 3 + 2];
        pl[448 + tid] = plane_max[tid * 3 + 0];
        pl[512 + tid] = plane_max[tid * 3 + 1];
        pl[576 + tid] = plane_max[tid * 3 + 2];
    }
    if (tid < 3) ctr[tid] = centers[tid];
    __syncthreads();

    const float cx = ctr[0], cy = ctr[1], cz = ctr[2];

    float4 poolv[8];
#pragma unroll
    for (int j = 0; j < 8; j++) poolv[j] = make_float4(0.f, 0.f, 0.f, 0.f);

    for (int t = blockIdx.x; t < NTILES; t += GRID) {
        const int gbase = t * TILE_M + 64 * grp;

        // ---- load 64-pt feature half -> f16 A
        {
            const float4* src = (const float4*)(feature + (size_t)gbase * 128);
#pragma unroll
            for (int jj = 0; jj < 8; jj++) {
                const int idx = gtid + jj * 256;         // 2048 float4
                const int pt  = idx >> 5, k4 = idx & 31; // k0 = 4*k4
                const float4 f = src[idx];
                const uint32_t a = swz(0, pt, k4 >> 1) + (uint32_t)((k4 & 1) * 8);
                *(uint2*)(smem + (aB - sb) + a) =
                    make_uint2(pack_h2(f.x, f.y), pack_h2(f.z, f.w));
            }
        }

        // ---- masks: warp computes its 8 planes for both 32-pt chunks
#pragma unroll
        for (int h = 0; h < 2; h++) {
            const int pt = gbase + 32 * h + lane;
            const float px = xyz[(size_t)pt * 3 + 0] + cx;
            const float py = xyz[(size_t)pt * 3 + 1] + cy;
            const float pz = xyz[(size_t)pt * 3 + 2] + cz;
#pragma unroll
            for (int j = 0; j < 8; j++) {
                const int p = 8 * wg + j;
                const float d = fabsf(px * pl[p] + py * pl[64 + p] + pz * pl[128 + p]
                                      - pl[192 + p]);
                bool ok = d < 0.05f;
                float mn, mx;
                mn = pl[256 + p]; mx = pl[448 + p];
                ok = ok && ((px >= mn && px < mx) || (mx == 0.f));
                mn = pl[320 + p]; mx = pl[512 + p];
                ok = ok && ((py >= mn && py < mx) || (mx == 0.f));
                mn = pl[384 + p]; mx = pl[576 + p];
                ok = ok && ((pz >= mn && pz < mx) || (mx == 0.f));
                const unsigned bal = __ballot_sync(0xffffffffu, ok);
                if (lane == 0) pmg[p * 2 + h] = bal;
            }
        }
        GBAR(barid);

        // ---- layer 1 ----
        float acc[2][4][4];
#pragma unroll
        for (int i = 0; i < 2; i++)
#pragma unroll
            for (int j = 0; j < 4; j++)
#pragma unroll
                for (int q = 0; q < 4; q++) acc[i][j][q] = 0.f;

        do_layer(aB, sb + OFF_W1, acc, r2, c2, lane);
        GBAR(barid);   // group done reading feature f16

        // ---- epilogue 1: +b1, relu, f16 back into A
#pragma unroll
        for (int i = 0; i < 2; i++)
#pragma unroll
            for (int h = 0; h < 2; h++) {
                const int row = 32 * r2 + 16 * i + 8 * h + g;
#pragma unroll
                for (int j = 0; j < 4; j++) {
                    const int col0 = 32 * c2 + 8 * j + 2 * tig;
                    const float2 bb = *(const float2*)&b1s[col0];
                    const float v0 = fmaxf(acc[i][j][2 * h + 0] + bb.x, 0.f);
                    const float v1 = fmaxf(acc[i][j][2 * h + 1] + bb.y, 0.f);
                    const uint32_t a = swz(0, row, 4 * c2 + j) + (uint32_t)(4 * tig);
                    *(uint32_t*)(smem + (aB - sb) + a) = pack_h2(v0, v1);
                }
            }
        GBAR(barid);

        // ---- layer 2 ----
#pragma unroll
        for (int i = 0; i < 2; i++)
#pragma unroll
            for (int j = 0; j < 4; j++)
#pragma unroll
                for (int q = 0; q < 4; q++) acc[i][j][q] = 0.f;

        do_layer(aB, sb + OFF_W2, acc, r2, c2, lane);
        // no barrier needed before epi2: Hf is a distinct region; A reads done
        // are only needed before NEXT tile's A write -> covered by pool barrier.

        // ---- epilogue 2: +b2, relu, f32 into Hf (16B-chunk xor swizzle)
#pragma unroll
        for (int i = 0; i < 2; i++)
#pragma unroll
            for (int h = 0; h < 2; h++) {
                const int row = 32 * r2 + 16 * i + 8 * h + g;
                const int rsw = (row & 7) << 1;
#pragma unroll
                for (int j = 0; j < 4; j++) {
                    const int col0 = 32 * c2 + 8 * j + 2 * tig;
                    const float2 bb = *(const float2*)&b2s[col0];
                    float2 v;
                    v.x = fmaxf(acc[i][j][2 * h + 0] + bb.x, 0.f);
                    v.y = fmaxf(acc[i][j][2 * h + 1] + bb.y, 0.f);
                    const int ch = 2 * (4 * c2 + j) + (tig >> 1);
                    const uint32_t off = (uint32_t)(row * 512 + ((ch ^ rsw) << 4)
                                                    + (tig & 1) * 8);
                    *(float2*)((char*)Hf + off) = v;
                }
            }
        GBAR(barid);

        // ---- pool: warp's 8 planes over this group's 64 points
#pragma unroll
        for (int j = 0; j < 8; j++) {
            const int p = 8 * wg + j;
#pragma unroll
            for (int h = 0; h < 2; h++) {
                unsigned bits = pmg[p * 2 + h];
                while (bits) {
                    const int i = __ffs(bits) - 1;
                    bits &= bits - 1;
                    const int pt = 32 * h + i;
                    const float4 v = *(const float4*)
                        &Hf[pt * 128 + ((lane ^ ((pt & 7) << 1)) << 2)];
                    poolv[j].x = fmaxf(poolv[j].x, v.x);
                    poolv[j].y = fmaxf(poolv[j].y, v.y);
                    poolv[j].z = fmaxf(poolv[j].z, v.z);
                    poolv[j].w = fmaxf(poolv[j].w, v.w);
                }
            }
        }
        GBAR(barid);   // pool done (Hf) and A reads done before next tile writes
    }

    // ---- merge (nonneg float max == uint max on float bits)
    {
        unsigned* o32 = (unsigned*)out;
#pragma unroll
        for (int j = 0; j < 8; j++) {
            const int p = 8 * wg + j;
            const int bidx = p * 128 + lane * 4;
            atomicMax(&o32[bidx + 0], __float_as_uint(poolv[j].x));
            atomicMax(&o32[bidx + 1], __float_as_uint(poolv[j].y));
            atomicMax(&o32[bidx + 2], __float_as_uint(poolv[j].z));
            atomicMax(&o32[bidx + 3], __float_as_uint(poolv[j].w));
        }
    }
}

__global__ void zero_out_kernel(float* __restrict__ out, int n) {
    const int i = blockIdx.x * blockDim.x + threadIdx.x;
    if (i < n) out[i] = 0.f;
}

extern "C" void kernel_launch(void* const* d_in, const int* in_sizes, int n_in,
                              void* d_out, int out_size)
{
    const float* feature      = (const float*)d_in[0];
    const float* xyz          = (const float*)d_in[1];
    const float* centers      = (const float*)d_in[2];
    const float* plane_center = (const float*)d_in[3];
    const float* plane_normal = (const float*)d_in[4];
    const float* plane_min    = (const float*)d_in[5];
    const float* plane_max    = (const float*)d_in[6];
    const float* W1           = (const float*)d_in[7];
    const float* g1           = (const float*)d_in[8];
    const float* b1           = (const float*)d_in[9];
    const float* W2           = (const float*)d_in[10];
    const float* g2           = (const float*)d_in[11];
    const float* b2           = (const float*)d_in[12];
    float* out = (float*)d_out;

    cudaFuncSetAttribute(plane_refine_h,
                         cudaFuncAttributeMaxDynamicSharedMemorySize, SMEM_BYTES);

    zero_out_kernel<<<(P * 128 + 255) / 256, 256>>>(out, P * 128);
    plane_refine_h<<<GRID, THREADS, SMEM_BYTES>>>(
        feature, xyz, centers, plane_center, plane_normal, plane_min, plane_max,
        W1, g1, b1, W2, g2, b2, out);
}

// round 8
// speedup vs baseline: 4.5663x; 1.0171x over previous
#include <cuda_runtime.h>
#include <cuda_fp16.h>
#include <cstdint>

// ---------------------------------------------------------------------------
// Plane_refine on sm_100: 2-layer pointwise MLP via fp16 mma.sync (f32 accum)
// + masked max-pool. 296 CTAs x 256 threads, 2 CTAs/SM for cross-CTA overlap.
// Each CTA iterates 64-pt x 128-dim tiles. Warp (r2=wg&1, c2=wg>>1) owns the
// 32x32 output block. f32 H2 buffer aliases A(f16) U H1(f16) - both dead by
// the time epilogue 2 writes.
// ---------------------------------------------------------------------------

constexpr int N_PTS   = 131072;
constexpr int TILE    = 64;
constexpr int NT      = N_PTS / TILE;     // 2048
constexpr int GRID    = 296;              // 2 per SM
constexpr int THREADS = 256;
constexpr int P       = 64;

// smem byte offsets. f16 rows: 128 f16 = 256 B, 16B-chunk XOR swizzle
// chunk' = chunk ^ (row & 7).
constexpr int OFF_W1  = 0;          // 32 KB
constexpr int OFF_W2  = 32768;      // 32 KB
constexpr int OFF_A   = 65536;      // 16 KB (64 rows x 256B) feature f16
constexpr int OFF_H1  = 81920;      // 16 KB H1 f16
// Hf (f32, 64 rows x 512B): rows 0-31 -> OFF_A, rows 32-63 -> OFF_H1
constexpr int OFF_MISC = 98304;
constexpr int OFF_B1   = OFF_MISC + 0;      // f32[128]
constexpr int OFF_B2   = OFF_MISC + 512;    // f32[128]
constexpr int OFF_PL   = OFF_MISC + 1024;   // f32[640]
constexpr int OFF_CTR  = OFF_MISC + 3584;   // f32[4]
constexpr int OFF_PMS  = OFF_MISC + 3600;   // u32[64][2]
constexpr int SMEM_BYTES = OFF_MISC + 4640; // 102,944 B -> 2 CTAs/SM

__device__ __forceinline__ uint32_t smem_u32(const void* p) {
    uint32_t a;
    asm("{ .reg .u64 t; cvta.to.shared.u64 t, %1; cvt.u32.u64 %0, t; }"
        : "=r"(a) : "l"(p));
    return a;
}

// byte address of 16B chunk `kc` (0..15) in row `row` of a swizzled f16 region
__device__ __forceinline__ uint32_t swz(uint32_t region, int row, int kc) {
    return region + (uint32_t)(row * 256) + (uint32_t)((kc ^ (row & 7)) << 4);
}

__device__ __forceinline__ uint32_t pack_h2(float a, float b) {
    __half2 h = __floats2half2_rn(a, b);   // a -> low 16 bits
    return *(uint32_t*)&h;
}

#define LDSM_X4(r0, r1, r2, r3, a) \
    asm volatile("ldmatrix.sync.aligned.m8n8.x4.shared.b16 {%0,%1,%2,%3}, [%4];" \
                 : "=r"(r0), "=r"(r1), "=r"(r2), "=r"(r3) : "r"(a))
#define MMA16816(d, a0, a1, a2, a3, b0, b1) \
    asm volatile("mma.sync.aligned.m16n8k16.row.col.f32.f16.f16.f32 " \
                 "{%0,%1,%2,%3}, {%4,%5,%6,%7}, {%8,%9}, {%0,%1,%2,%3};" \
                 : "+f"((d)[0]), "+f"((d)[1]), "+f"((d)[2]), "+f"((d)[3]) \
                 : "r"(a0), "r"(a1), "r"(a2), "r"(a3), "r"(b0), "r"(b1))

// One 64x128x128 layer for this warp's 32x32 block (single fp16 term).
__device__ __forceinline__ void do_layer(uint32_t aB, uint32_t wB,
                                         float acc[2][4][4],
                                         int r2, int c2, int lane)
{
    const int arow  = 32 * r2 + (lane & 15);
    const int abit  = (lane >> 4) & 1;
    const int rs    = arow & 7;
    const uint32_t aoff = (uint32_t)(arow * 256);
    const int bn    = 32 * c2 + (lane & 7) + (((lane >> 4) & 1) << 3);
    const int bbit  = (lane >> 3) & 1;
    const int ns    = bn & 7;
    const uint32_t boff = (uint32_t)(bn * 256);

#pragma unroll
    for (int kk = 0; kk < 8; kk++) {
        const uint32_t kcA = (uint32_t)(((2 * kk + abit) ^ rs) << 4);
        const uint32_t kcB = (uint32_t)(((2 * kk + bbit) ^ ns) << 4);
        uint32_t a[8], b[8];
        LDSM_X4(a[0], a[1], a[2], a[3], aB + aoff + kcA);
        LDSM_X4(a[4], a[5], a[6], a[7], aB + aoff + 4096 + kcA);
        LDSM_X4(b[0], b[1], b[2], b[3], wB + boff + kcB);
        LDSM_X4(b[4], b[5], b[6], b[7], wB + boff + 4096 + kcB);
#pragma unroll
        for (int i = 0; i < 2; i++) {
            const uint32_t* A = &a[4 * i];
#pragma unroll
            for (int j = 0; j < 4; j++)
                MMA16816(acc[i][j], A[0], A[1], A[2], A[3], b[2 * j], b[2 * j + 1]);
        }
    }
}

__global__ void __launch_bounds__(THREADS, 2)
plane_refine_2c(const float* __restrict__ feature, const float* __restrict__ xyz,
                const float* __restrict__ centers,
                const float* __restrict__ plane_center, const float* __restrict__ plane_normal,
                const float* __restrict__ plane_min, const float* __restrict__ plane_max,
                const float* __restrict__ W1, const float* __restrict__ g1,
                const float* __restrict__ b1,
                const float* __restrict__ W2, const float* __restrict__ g2,
                const float* __restrict__ b2,
                float* __restrict__ out)
{
    extern __shared__ char smem[];
    const uint32_t sb = smem_u32(smem);

    float*    b1s = (float*)(smem + OFF_B1);
    float*    b2s = (float*)(smem + OFF_B2);
    float*    pl  = (float*)(smem + OFF_PL);
    float*    ctr = (float*)(smem + OFF_CTR);
    unsigned* pms = (unsigned*)(smem + OFF_PMS);

    const int tid  = threadIdx.x;
    const int lane = tid & 31;
    const int wg   = tid >> 5;      // 0..7
    const int r2   = wg & 1;
    const int c2   = wg >> 1;
    const int g    = lane >> 2;
    const int tig  = lane & 3;

    const uint32_t aB = sb + OFF_A;

    // ---- prologue: weights (fold g, -> f16, swizzled), consts
    for (int idx = tid; idx < 16384; idx += THREADS) {
        const int o = idx >> 7, k = idx & 127;
        const uint32_t a1 = swz(0, o, k >> 3) + (uint32_t)((k & 7) * 2);
        *(__half*)(smem + a1 + OFF_W1) = __float2half_rn(W1[idx] * g1[o]);
        *(__half*)(smem + a1 + OFF_W2) = __float2half_rn(W2[idx] * g2[o]);
    }
    if (tid < 128) { b1s[tid] = b1[tid]; b2s[tid] = b2[tid]; }
    if (tid < P) {
        const float nx = plane_normal[tid * 3 + 0];
        const float ny = plane_normal[tid * 3 + 1];
        const float nz = plane_normal[tid * 3 + 2];
        pl[tid]       = nx;  pl[64 + tid]  = ny;  pl[128 + tid] = nz;
        pl[192 + tid] = plane_center[tid * 3 + 0] * nx
                      + plane_center[tid * 3 + 1] * ny
                      + plane_center[tid * 3 + 2] * nz;
        pl[256 + tid] = plane_min[tid * 3 + 0];
        pl[320 + tid] = plane_min[tid * 3 + 1];
        pl[384 + tid] = plane_min[tid * 3 + 2];
        pl[448 + tid] = plane_max[tid * 3 + 0];
        pl[512 + tid] = plane_max[tid * 3 + 1];
        pl[576 + tid] = plane_max[tid * 3 + 2];
    }
    if (tid < 3) ctr[tid] = centers[tid];
    __syncthreads();

    const float cx = ctr[0], cy = ctr[1], cz = ctr[2];

    // warp owns planes 8*wg..8*wg+7; lane owns dims 4*lane..4*lane+3
    float4 poolv[8];
#pragma unroll
    for (int j = 0; j < 8; j++) poolv[j] = make_float4(0.f, 0.f, 0.f, 0.f);

    for (int t = blockIdx.x; t < NT; t += GRID) {
        const int gbase = t * TILE;

        // ---- load 64-pt feature tile -> f16 A
        {
            const float4* src = (const float4*)(feature + (size_t)gbase * 128);
#pragma unroll
            for (int jj = 0; jj < 8; jj++) {
                const int idx = tid + jj * THREADS;      // 2048 float4
                const int pt  = idx >> 5, k4 = idx & 31; // k0 = 4*k4
                const float4 f = src[idx];
                const uint32_t a = swz(OFF_A, pt, k4 >> 1) + (uint32_t)((k4 & 1) * 8);
                *(uint2*)(smem + a) = make_uint2(pack_h2(f.x, f.y), pack_h2(f.z, f.w));
            }
        }

        // ---- masks: warp computes its 8 planes for both 32-pt chunks
#pragma unroll
        for (int h = 0; h < 2; h++) {
            const int pt = gbase + 32 * h + lane;
            const float px = xyz[(size_t)pt * 3 + 0] + cx;
            const float py = xyz[(size_t)pt * 3 + 1] + cy;
            const float pz = xyz[(size_t)pt * 3 + 2] + cz;
#pragma unroll
            for (int j = 0; j < 8; j++) {
                const int p = 8 * wg + j;
                const float d = fabsf(px * pl[p] + py * pl[64 + p] + pz * pl[128 + p]
                                      - pl[192 + p]);
                bool ok = d < 0.05f;
                float mn, mx;
                mn = pl[256 + p]; mx = pl[448 + p];
                ok = ok && ((px >= mn && px < mx) || (mx == 0.f));
                mn = pl[320 + p]; mx = pl[512 + p];
                ok = ok && ((py >= mn && py < mx) || (mx == 0.f));
                mn = pl[384 + p]; mx = pl[576 + p];
                ok = ok && ((pz >= mn && pz < mx) || (mx == 0.f));
                const unsigned bal = __ballot_sync(0xffffffffu, ok);
                if (lane == 0) pms[p * 2 + h] = bal;
            }
        }
        __syncthreads();   // A ready (and prev tile fully done)

        // ---- layer 1 ----
        float acc[2][4][4];
#pragma unroll
        for (int i = 0; i < 2; i++)
#pragma unroll
            for (int j = 0; j < 4; j++)
#pragma unroll
                for (int q = 0; q < 4; q++) acc[i][j][q] = 0.f;

        do_layer(aB, sb + OFF_W1, acc, r2, c2, lane);

        // ---- epilogue 1: +b1, relu, f16 into H1 (separate region, no bar needed
        //      between own layer1 and epi1; cross-warp ordering via next bar)
#pragma unroll
        for (int i = 0; i < 2; i++)
#pragma unroll
            for (int h = 0; h < 2; h++) {
                const int row = 32 * r2 + 16 * i + 8 * h + g;
#pragma unroll
                for (int j = 0; j < 4; j++) {
                    const int col0 = 32 * c2 + 8 * j + 2 * tig;
                    const float2 bb = *(const float2*)&b1s[col0];
                    const float v0 = fmaxf(acc[i][j][2 * h + 0] + bb.x, 0.f);
                    const float v1 = fmaxf(acc[i][j][2 * h + 1] + bb.y, 0.f);
                    const uint32_t a = swz(OFF_H1, row, 4 * c2 + j) + (uint32_t)(4 * tig);
                    *(uint32_t*)(smem + a) = pack_h2(v0, v1);
                }
            }
        __syncthreads();   // H1 ready; also: all warps done reading A

        // ---- layer 2 ----
#pragma unroll
        for (int i = 0; i < 2; i++)
#pragma unroll
            for (int j = 0; j < 4; j++)
#pragma unroll
                for (int q = 0; q < 4; q++) acc[i][j][q] = 0.f;

        do_layer(sb + OFF_H1, sb + OFF_W2, acc, r2, c2, lane);
        __syncthreads();   // all warps done reading H1 (epi2 will overwrite A & H1)

        // ---- epilogue 2: +b2, relu, f32 into Hf = A(rows 0-31) U H1(rows 32-63)
#pragma unroll
        for (int i = 0; i < 2; i++)
#pragma unroll
            for (int h = 0; h < 2; h++) {
                const int row = 32 * r2 + 16 * i + 8 * h + g;
                const uint32_t reg = (row < 32) ? OFF_A : OFF_H1;
                const int rr = row & 31;
                const int rsw = (rr & 7) << 1;
#pragma unroll
                for (int j = 0; j < 4; j++) {
                    const int col0 = 32 * c2 + 8 * j + 2 * tig;
                    const float2 bb = *(const float2*)&b2s[col0];
                    float2 v;
                    v.x = fmaxf(acc[i][j][2 * h + 0] + bb.x, 0.f);
                    v.y = fmaxf(acc[i][j][2 * h + 1] + bb.y, 0.f);
                    const int ch = 2 * (4 * c2 + j) + (tig >> 1);
                    const uint32_t off = (uint32_t)(rr * 512 + ((ch ^ rsw) << 4)
                                                    + (tig & 1) * 8);
                    *(float2*)(smem + reg + off) = v;
                }
            }
        __syncthreads();   // Hf ready

        // ---- pool: warp's 8 planes over 64 points
#pragma unroll
        for (int j = 0; j < 8; j++) {
            const int p = 8 * wg + j;
#pragma unroll
            for (int h = 0; h < 2; h++) {
                unsigned bits = pms[p * 2 + h];
                const char* reg = smem + (h ? OFF_H1 : OFF_A);
                while (bits) {
                    const int i = __ffs(bits) - 1;
                    bits &= bits - 1;
                    const float4 v = *(const float4*)
                        (reg + i * 512 + (((lane ^ ((i & 7) << 1)) << 2)) * 4);
                    poolv[j].x = fmaxf(poolv[j].x, v.x);
                    poolv[j].y = fmaxf(poolv[j].y, v.y);
                    poolv[j].z = fmaxf(poolv[j].z, v.z);
                    poolv[j].w = fmaxf(poolv[j].w, v.w);
                }
            }
        }
        __syncthreads();   // pool done; next tile may overwrite A/H1/pms
    }

    // ---- merge (nonneg float max == uint max on float bits)
    {
        unsigned* o32 = (unsigned*)out;
#pragma unroll
        for (int j = 0; j < 8; j++) {
            const int p = 8 * wg + j;
            const int bidx = p * 128 + lane * 4;
            atomicMax(&o32[bidx + 0], __float_as_uint(poolv[j].x));
            atomicMax(&o32[bidx + 1], __float_as_uint(poolv[j].y));
            atomicMax(&o32[bidx + 2], __float_as_uint(poolv[j].z));
            atomicMax(&o32[bidx + 3], __float_as_uint(poolv[j].w));
        }
    }
}

__global__ void zero_out_kernel(float* __restrict__ out, int n) {
    const int i = blockIdx.x * blockDim.x + threadIdx.x;
    if (i < n) out[i] = 0.f;
}

extern "C" void kernel_launch(void* const* d_in, const int* in_sizes, int n_in,
                              void* d_out, int out_size)
{
    const float* feature      = (const float*)d_in[0];
    const float* xyz          = (const float*)d_in[1];
    const float* centers      = (const float*)d_in[2];
    const float* plane_center = (const float*)d_in[3];
    const float* plane_normal = (const float*)d_in[4];
    const float* plane_min    = (const float*)d_in[5];
    const float* plane_max    = (const float*)d_in[6];
    const float* W1           = (const float*)d_in[7];
    const float* g1           = (const float*)d_in[8];
    const float* b1           = (const float*)d_in[9];
    const float* W2           = (const float*)d_in[10];
    const float* g2           = (const float*)d_in[11];
    const float* b2           = (const float*)d_in[12];
    float* out = (float*)d_out;

    cudaFuncSetAttribute(plane_refine_2c,
                         cudaFuncAttributeMaxDynamicSharedMemorySize, SMEM_BYTES);

    zero_out_kernel<<<(P * 128 + 255) / 256, 256>>>(out, P * 128);
    plane_refine_2c<<<GRID, THREADS, SMEM_BYTES>>>(
        feature, xyz, centers, plane_center, plane_normal, plane_min, plane_max,
        W1, g1, b1, W2, g2, b2, out);
}